// round 2
// baseline (speedup 1.0000x reference)
#include <cuda_runtime.h>
#include <cuda_bf16.h>

#define NROWS 65536      // B*K = 4096*16
#define DDIM  256
#define NCODE 512
#define NDTOT (NROWS*DDIM)

// ---------------- device scratch (static: no allocations allowed) ----------------
__device__ float g_Z[NDTOT];            // 64 MB: z = hidden @ W_in^T
__device__ float g_Cout[NCODE*DDIM];    // codebook @ W_out^T
__device__ float g_Cnorm[NCODE];        // |c|^2
__device__ float g_maskf[NROWS];        // active_mask as float 0/1
__device__ int   g_idx[NROWS];          // argmin code per row
__device__ float g_partial[512];        // per-CTA loss partial sums

// ---------------- f32x2 helpers (packed dual-FMA: 2x fp32 rate, bit-exact fp32) ----
__device__ __forceinline__ unsigned long long pk2(float lo, float hi) {
    unsigned long long r;
    asm("mov.b64 %0, {%1, %2};" : "=l"(r) : "f"(lo), "f"(hi));
    return r;
}
__device__ __forceinline__ void unpk2(unsigned long long v, float& lo, float& hi) {
    asm("mov.b64 {%0, %1}, %2;" : "=f"(lo), "=f"(hi) : "l"(v));
}
__device__ __forceinline__ void ffma2(unsigned long long& acc, unsigned long long a,
                                      unsigned long long b) {
    asm("fma.rn.f32x2 %0, %1, %2, %0;" : "+l"(acc) : "l"(a), "l"(b));
}
__device__ __forceinline__ unsigned f2key(float f) {
    unsigned u = __float_as_uint(f);
    return (u & 0x80000000u) ? ~u : (u | 0x80000000u);
}
__device__ __forceinline__ float key2f(unsigned k) {
    unsigned u = (k & 0x80000000u) ? (k ^ 0x80000000u) : ~k;
    return __uint_as_float(u);
}

// ---------------- mask dtype detection + conversion ----------------
// active_mask is bool in the reference; the serialized dtype is ambiguous.
// Classify byte pattern over the first 65536 bytes (safe lower bound for all
// candidate dtypes), then convert with (!=0 -> 1.0f) semantics.
__global__ void mask_conv(const void* __restrict__ mp) {
    __shared__ int s_big, s_c1, s_cA;
    const unsigned char* b = (const unsigned char*)mp;
    int tid = threadIdx.x;
    if (tid == 0) { s_big = 0; s_c1 = 0; s_cA = 0; }
    __syncthreads();
    int big = 0, c1 = 0, cA = 0;
    for (int i = tid; i < 65536; i += 256) {
        unsigned char v = b[i];
        if (v > 1) big++;
        if (v) {
            if ((i & 3) == 1) c1++;
            if ((i & 3) != 0) cA++;
        }
    }
    if (big) atomicAdd(&s_big, big);
    if (c1)  atomicAdd(&s_c1, c1);
    if (cA)  atomicAdd(&s_cA, cA);
    __syncthreads();
    // mode: 0=int32, 1=float32, 2=uint8/bool, 3=bf16
    int mode = s_big ? (s_c1 ? 3 : 1) : (s_cA ? 2 : 0);
    for (int i = tid; i < NROWS; i += 256) {
        bool nz;
        if (mode == 0)      nz = (((const int*)mp)[i] != 0);
        else if (mode == 1) nz = (((const float*)mp)[i] != 0.0f);
        else if (mode == 3) nz = ((b[2 * i] | b[2 * i + 1]) != 0);
        else                nz = (b[i] != 0);
        g_maskf[i] = nz ? 1.0f : 0.0f;
    }
}

// ---------------- |c|^2 per code (one warp per code) ----------------
__global__ void cnorm_k(const float* __restrict__ cb) {
    int w = (blockIdx.x * blockDim.x + threadIdx.x) >> 5;
    int lane = threadIdx.x & 31;
    if (w >= NCODE) return;
    const float* r = cb + (size_t)w * DDIM;
    float s = 0.f;
    #pragma unroll
    for (int j = 0; j < 2; j++) {
        float4 v = *(const float4*)(r + lane * 8 + j * 4);
        s += v.x * v.x + v.y * v.y + v.z * v.z + v.w * v.w;
    }
    #pragma unroll
    for (int o = 16; o > 0; o >>= 1) s += __shfl_xor_sync(0xffffffffu, s, o);
    if (lane == 0) g_Cnorm[w] = s;
}

// ---------------- GEMM  C[m,n] = sum_d A[m,d] * B[n,d]  (both K-major) ----------
// BM=BN=128, BK=16, 256 threads (16x16), 8x8 micro-tile via f32x2 (row-paired acc).
// Bs stores every value DUPLICATED so ld.shared.v2.u64 yields {b,b} pairs directly.
__launch_bounds__(256, 2)
__global__ void gemm_abt(const float* __restrict__ A, const float* __restrict__ B,
                         float* __restrict__ Cm) {
    __shared__ float As[16][132];
    __shared__ float Bs[16][264];
    int tid = threadIdx.x;
    int tx = tid & 15, ty = tid >> 4;
    int m0 = blockIdx.y * 128, n0 = blockIdx.x * 128;
    int lr = tid >> 2, cg = tid & 3;

    unsigned long long acc[4][8];
    #pragma unroll
    for (int i = 0; i < 4; i++)
        #pragma unroll
        for (int j = 0; j < 8; j++) acc[i][j] = 0ull;

    const float* Ab = A + (size_t)(m0 + lr) * DDIM + cg * 4;
    const float* Bb = B + (size_t)(n0 + lr) * DDIM + cg * 4;

    float4 va0 = *(const float4*)(Ab);
    float4 va1 = *(const float4*)(Ab + (size_t)64 * DDIM);
    float4 vb0 = *(const float4*)(Bb);
    float4 vb1 = *(const float4*)(Bb + (size_t)64 * DDIM);

    for (int kk = 0; kk < 16; kk++) {
        __syncthreads();
        #pragma unroll
        for (int j = 0; j < 4; j++) {
            float a0 = ((const float*)&va0)[j], a1 = ((const float*)&va1)[j];
            float b0 = ((const float*)&vb0)[j], b1 = ((const float*)&vb1)[j];
            As[cg * 4 + j][lr]      = a0;
            As[cg * 4 + j][lr + 64] = a1;
            *(float2*)&Bs[cg * 4 + j][2 * lr]        = make_float2(b0, b0);
            *(float2*)&Bs[cg * 4 + j][2 * (lr + 64)] = make_float2(b1, b1);
        }
        __syncthreads();
        int kn = (kk < 15) ? (kk + 1) : 15;
        va0 = *(const float4*)(Ab + kn * 16);
        va1 = *(const float4*)(Ab + (size_t)64 * DDIM + kn * 16);
        vb0 = *(const float4*)(Bb + kn * 16);
        vb1 = *(const float4*)(Bb + (size_t)64 * DDIM + kn * 16);

        #pragma unroll
        for (int k = 0; k < 16; k++) {
            ulonglong2 a01 = *(ulonglong2*)&As[k][ty * 8];
            ulonglong2 a23 = *(ulonglong2*)&As[k][ty * 8 + 4];
            unsigned long long av[4] = {a01.x, a01.y, a23.x, a23.y};
            ulonglong2 b0 = *(ulonglong2*)&Bs[k][tx * 16];
            ulonglong2 b1 = *(ulonglong2*)&Bs[k][tx * 16 + 4];
            ulonglong2 b2 = *(ulonglong2*)&Bs[k][tx * 16 + 8];
            ulonglong2 b3 = *(ulonglong2*)&Bs[k][tx * 16 + 12];
            unsigned long long bv[8] = {b0.x, b0.y, b1.x, b1.y, b2.x, b2.y, b3.x, b3.y};
            #pragma unroll
            for (int i = 0; i < 4; i++)
                #pragma unroll
                for (int j = 0; j < 8; j++) ffma2(acc[i][j], av[i], bv[j]);
        }
    }
    #pragma unroll
    for (int i = 0; i < 4; i++)
        #pragma unroll
        for (int j = 0; j < 8; j++) {
            float lo, hi;
            unpk2(acc[i][j], lo, hi);
            int row = m0 + ty * 8 + 2 * i;
            int col = n0 + tx * 8 + j;
            Cm[(size_t)row * DDIM + col]       = lo;
            Cm[(size_t)(row + 1) * DDIM + col] = hi;
        }
}

// ---------------- distance + argmin: for each row min over 512 codes of
// s = |c|^2 - 2 z.c ; also accumulates |z|^2 per row on the first pass, and
// deterministic per-CTA loss partials (min dist = s_min + |z|^2). -------------
__launch_bounds__(256, 2)
__global__ void dist_argmin(const float* __restrict__ Cb) {
    __shared__ float As[16][132];
    __shared__ float Bs[16][264];
    __shared__ unsigned long long minpack[128];
    __shared__ float znp[128][4];
    __shared__ float red[128];

    int tid = threadIdx.x;
    int tx = tid & 15, ty = tid >> 4;
    int m0 = blockIdx.x * 128;
    int lr = tid >> 2, cg = tid & 3;

    if (tid < 128) minpack[tid] = 0xFFFFFFFFFFFFFFFFull;
    float zs0 = 0.f, zs1 = 0.f;

    const float* Ab = g_Z + (size_t)(m0 + lr) * DDIM + cg * 4;

    for (int cc = 0; cc < 4; cc++) {
        unsigned long long acc[4][8];
        #pragma unroll
        for (int i = 0; i < 4; i++)
            #pragma unroll
            for (int j = 0; j < 8; j++) acc[i][j] = 0ull;

        const float* Bb = Cb + (size_t)(cc * 128 + lr) * DDIM + cg * 4;
        float4 va0 = *(const float4*)(Ab);
        float4 va1 = *(const float4*)(Ab + (size_t)64 * DDIM);
        float4 vb0 = *(const float4*)(Bb);
        float4 vb1 = *(const float4*)(Bb + (size_t)64 * DDIM);

        for (int kk = 0; kk < 16; kk++) {
            __syncthreads();
            #pragma unroll
            for (int j = 0; j < 4; j++) {
                float a0 = ((const float*)&va0)[j], a1 = ((const float*)&va1)[j];
                float b0 = ((const float*)&vb0)[j], b1 = ((const float*)&vb1)[j];
                As[cg * 4 + j][lr]      = a0;
                As[cg * 4 + j][lr + 64] = a1;
                *(float2*)&Bs[cg * 4 + j][2 * lr]        = make_float2(b0, b0);
                *(float2*)&Bs[cg * 4 + j][2 * (lr + 64)] = make_float2(b1, b1);
            }
            if (cc == 0) {  // |z|^2 partials: this thread's 4-col group, 2 rows
                zs0 += va0.x * va0.x + va0.y * va0.y + va0.z * va0.z + va0.w * va0.w;
                zs1 += va1.x * va1.x + va1.y * va1.y + va1.z * va1.z + va1.w * va1.w;
            }
            __syncthreads();
            int kn = (kk < 15) ? (kk + 1) : 15;
            va0 = *(const float4*)(Ab + kn * 16);
            va1 = *(const float4*)(Ab + (size_t)64 * DDIM + kn * 16);
            vb0 = *(const float4*)(Bb + kn * 16);
            vb1 = *(const float4*)(Bb + (size_t)64 * DDIM + kn * 16);

            #pragma unroll
            for (int k = 0; k < 16; k++) {
                ulonglong2 a01 = *(ulonglong2*)&As[k][ty * 8];
                ulonglong2 a23 = *(ulonglong2*)&As[k][ty * 8 + 4];
                unsigned long long av[4] = {a01.x, a01.y, a23.x, a23.y};
                ulonglong2 b0 = *(ulonglong2*)&Bs[k][tx * 16];
                ulonglong2 b1 = *(ulonglong2*)&Bs[k][tx * 16 + 4];
                ulonglong2 b2 = *(ulonglong2*)&Bs[k][tx * 16 + 8];
                ulonglong2 b3 = *(ulonglong2*)&Bs[k][tx * 16 + 12];
                unsigned long long bv[8] = {b0.x, b0.y, b1.x, b1.y, b2.x, b2.y, b3.x, b3.y};
                #pragma unroll
                for (int i = 0; i < 4; i++)
                    #pragma unroll
                    for (int j = 0; j < 8; j++) ffma2(acc[i][j], av[i], bv[j]);
            }
        }

        // epilogue for this code chunk: per-row min of |c|^2 - 2*dot
        float cn[8];
        #pragma unroll
        for (int j = 0; j < 8; j++) cn[j] = __ldg(&g_Cnorm[cc * 128 + tx * 8 + j]);
        #pragma unroll
        for (int i = 0; i < 4; i++) {
            float bl = 3.4e38f, bh = 3.4e38f;
            int jl = 0, jh = 0;
            #pragma unroll
            for (int j = 0; j < 8; j++) {
                float lo, hi;
                unpk2(acc[i][j], lo, hi);
                float sl = cn[j] - 2.0f * lo;
                float sh = cn[j] - 2.0f * hi;
                if (sl < bl) { bl = sl; jl = j; }
                if (sh < bh) { bh = sh; jh = j; }
            }
            unsigned long long pl =
                (((unsigned long long)f2key(bl)) << 32) | (unsigned)(cc * 128 + tx * 8 + jl);
            unsigned long long ph =
                (((unsigned long long)f2key(bh)) << 32) | (unsigned)(cc * 128 + tx * 8 + jh);
            atomicMin(&minpack[ty * 8 + 2 * i], pl);
            atomicMin(&minpack[ty * 8 + 2 * i + 1], ph);
        }
    }

    znp[lr][cg]      = zs0;
    znp[lr + 64][cg] = zs1;
    __syncthreads();
    if (tid < 128) {
        float zn = znp[tid][0] + znp[tid][1] + znp[tid][2] + znp[tid][3];
        unsigned long long pkv = minpack[tid];
        float minv = key2f((unsigned)(pkv >> 32));
        g_idx[m0 + tid] = (int)(pkv & 0xffffffffull);
        red[tid] = minv + zn;   // = min_c |z - c|^2
    }
    __syncthreads();
    #pragma unroll
    for (int s = 64; s > 0; s >>= 1) {
        if (tid < s) red[tid] += red[tid + s];
        __syncthreads();
    }
    if (tid == 0) g_partial[blockIdx.x] = red[0];
}

// ---------------- finalize: h = hidden + mask*Cout[idx]; LayerNorm; loss ------
__global__ void finalize_k(const float* __restrict__ hidden,
                           const float* __restrict__ gamma,
                           const float* __restrict__ beta,
                           float* __restrict__ out, int out_size) {
    int bid = blockIdx.x;
    if (bid == 8192) {  // deterministic loss reduction
        __shared__ float r[256];
        int t = threadIdx.x;
        r[t] = g_partial[t] + g_partial[t + 256];
        __syncthreads();
        #pragma unroll
        for (int s = 128; s > 0; s >>= 1) {
            if (t < s) r[t] += r[t + s];
            __syncthreads();
        }
        if (t == 0 && out_size > NDTOT)
            out[NDTOT] = 1.25f * (r[0] / 16777216.0f);
        return;
    }
    int w = threadIdx.x >> 5, lane = threadIdx.x & 31;
    int row = bid * 8 + w;
    int idx = g_idx[row];
    float mf = g_maskf[row];
    const float* hr = hidden + (size_t)row * DDIM;
    const float* cr = g_Cout + (size_t)idx * DDIM;
    float4 h0 = *(const float4*)(hr + lane * 8);
    float4 h1 = *(const float4*)(hr + lane * 8 + 4);
    float4 c0 = *(const float4*)(cr + lane * 8);
    float4 c1 = *(const float4*)(cr + lane * 8 + 4);
    h0.x += mf * c0.x; h0.y += mf * c0.y; h0.z += mf * c0.z; h0.w += mf * c0.w;
    h1.x += mf * c1.x; h1.y += mf * c1.y; h1.z += mf * c1.z; h1.w += mf * c1.w;

    float s = h0.x + h0.y + h0.z + h0.w + h1.x + h1.y + h1.z + h1.w;
    float q = h0.x * h0.x + h0.y * h0.y + h0.z * h0.z + h0.w * h0.w +
              h1.x * h1.x + h1.y * h1.y + h1.z * h1.z + h1.w * h1.w;
    #pragma unroll
    for (int o = 16; o > 0; o >>= 1) {
        s += __shfl_xor_sync(0xffffffffu, s, o);
        q += __shfl_xor_sync(0xffffffffu, q, o);
    }
    float mu = s * (1.0f / 256.0f);
    float var = q * (1.0f / 256.0f) - mu * mu;
    float rs = rsqrtf(var + 1e-5f);

    float4 g0 = *(const float4*)(gamma + lane * 8);
    float4 g1 = *(const float4*)(gamma + lane * 8 + 4);
    float4 b0 = *(const float4*)(beta + lane * 8);
    float4 b1 = *(const float4*)(beta + lane * 8 + 4);
    float4 o0, o1;
    o0.x = (h0.x - mu) * rs * g0.x + b0.x;
    o0.y = (h0.y - mu) * rs * g0.y + b0.y;
    o0.z = (h0.z - mu) * rs * g0.z + b0.z;
    o0.w = (h0.w - mu) * rs * g0.w + b0.w;
    o1.x = (h1.x - mu) * rs * g1.x + b1.x;
    o1.y = (h1.y - mu) * rs * g1.y + b1.y;
    o1.z = (h1.z - mu) * rs * g1.z + b1.z;
    o1.w = (h1.w - mu) * rs * g1.w + b1.w;
    *(float4*)(out + (size_t)row * DDIM + lane * 8)     = o0;
    *(float4*)(out + (size_t)row * DDIM + lane * 8 + 4) = o1;
}

// ---------------- launch ----------------
extern "C" void kernel_launch(void* const* d_in, const int* in_sizes, int n_in,
                              void* d_out, int out_size) {
    const float* hidden   = (const float*)d_in[0];
    const void*  maskp    = d_in[1];
    const float* codebook = (const float*)d_in[2];
    const float* W_in     = (const float*)d_in[3];
    const float* W_out    = (const float*)d_in[4];
    const float* gamma    = (const float*)d_in[5];
    const float* beta     = (const float*)d_in[6];
    float* out = (float*)d_out;

    void *zp = nullptr, *cop = nullptr;
    cudaGetSymbolAddress(&zp, g_Z);
    cudaGetSymbolAddress(&cop, g_Cout);

    mask_conv<<<1, 256>>>(maskp);
    cnorm_k<<<64, 256>>>(codebook);
    gemm_abt<<<dim3(2, 4), 256>>>(codebook, W_out, (float*)cop);   // Cout precompute
    gemm_abt<<<dim3(2, 512), 256>>>(hidden, W_in, (float*)zp);     // z = H @ W_in^T
    dist_argmin<<<512, 256>>>(codebook);
    finalize_k<<<8193, 256>>>(hidden, gamma, beta, out, out_size);
}